// round 16
// baseline (speedup 1.0000x reference)
#include <cuda_runtime.h>
#include <cuda_bf16.h>
#include <cstdint>
#include <cstddef>

#define Hh   16
#define Dd   1024
#define DHd  64
#define Bb   4
#define Nn   2048
#define MTOT (Bb*Nn)   // 8192

// ---------------- scratch (static device globals; no allocation) ----------------
__device__ __nv_bfloat16 g_qh[(size_t)Bb*Hh*Nn*DHd];   // (b,h,n,dh)  Q*0.125 hi
__device__ __nv_bfloat16 g_ql[(size_t)Bb*Hh*Nn*DHd];   //             Q*0.125 lo
__device__ __nv_bfloat16 g_kh[(size_t)Bb*Hh*Nn*DHd];   // (b,h,n,dh)  K hi
__device__ __nv_bfloat16 g_kl[(size_t)Bb*Hh*Nn*DHd];
__device__ __nv_bfloat16 g_vh[(size_t)Bb*Hh*Nn*DHd];   // (b,h,dh,n)  V^T hi
__device__ __nv_bfloat16 g_vl[(size_t)Bb*Hh*Nn*DHd];
__device__ float g_ctx[(size_t)MTOT*Dd];                // (b,n,h*dh)

__device__ __forceinline__ uint32_t f2tf32(float x) {
    uint32_t r;
    asm("cvt.rna.tf32.f32 %0, %1;" : "=r"(r) : "f"(x));
    return r;
}
// pack two floats -> bf16x2 (lo half = first element)
__device__ __forceinline__ uint32_t pk(float lo, float hi) {
    __nv_bfloat162 h = __float22bfloat162_rn(make_float2(lo, hi));
    return *(uint32_t*)&h;
}
__device__ __forceinline__ float rlo(float f, uint32_t p) { return f - __uint_as_float(p << 16); }
__device__ __forceinline__ float rhi(float f, uint32_t p) { return f - __uint_as_float(p & 0xffff0000u); }

#define MMA_BF16(d, a, b0, b1) \
    asm volatile("mma.sync.aligned.m16n8k16.row.col.f32.bf16.bf16.f32 " \
        "{%0,%1,%2,%3},{%4,%5,%6,%7},{%8,%9},{%0,%1,%2,%3};" \
        : "+f"((d)[0]), "+f"((d)[1]), "+f"((d)[2]), "+f"((d)[3]) \
        : "r"((a)[0]), "r"((a)[1]), "r"((a)[2]), "r"((a)[3]), "r"(b0), "r"(b1))

#define LDMX4(r, addr) \
    asm volatile("ldmatrix.sync.aligned.m8n8.x4.shared.b16 {%0,%1,%2,%3}, [%4];" \
        : "=r"((r)[0]), "=r"((r)[1]), "=r"((r)[2]), "=r"((r)[3]) : "r"(addr))

__device__ __forceinline__ uint32_t smem_u32(const void* p) {
    uint32_t a;
    asm("{ .reg .u64 t; cvta.to.shared.u64 t, %1; cvt.u32.u64 %0, t; }" : "=r"(a) : "l"(p));
    return a;
}
__device__ __forceinline__ void cp16(uint32_t s, const void* g) {
    asm volatile("cp.async.ca.shared.global [%0], [%1], 16;" :: "r"(s), "l"(g));
}
#define CP_COMMIT() asm volatile("cp.async.commit_group;")
#define CP_WAIT0()  asm volatile("cp.async.wait_group 0;")

// ====== tf32 mma.sync NT GEMM: C = A(M,K) * W(N,K)^T ; 128x128 tile, K=1024 =====
// Double-buffered smem (dynamic 73728 B). 8 warps 4(M)x2(N), warp tile 32x64.
// MODE 0: C fp32 row-major (M x 1024).
// MODE 1: Q -> (b,h,n,dh) bf16 hi/lo, scaled 0.125.   MODE 2: K -> same, unscaled.
// MODE 3: V -> (b,h,dh,n) bf16 hi/lo (transposed).
template<int MODE>
__global__ __launch_bounds__(256)
void gemm_mma(const float* __restrict__ A, const float* __restrict__ W,
              float* __restrict__ C, __nv_bfloat16* __restrict__ Ch,
              __nv_bfloat16* __restrict__ Cl)
{
    extern __shared__ float gsm[];   // [2][A 128*36 | B 128*36]

    const int tid  = threadIdx.x;
    const int wid  = tid >> 5;
    const int lane = tid & 31;
    const int bx = blockIdx.x;     // N tile (0..7)
    const int by = blockIdx.y;     // M tile (0..63)

    const int wm = (wid >> 1) * 32;
    const int wn = (wid & 1)  * 64;
    const int gq = lane >> 2;
    const int j4 = lane & 3;

    const int cr = tid >> 1;
    const int cc = (tid & 1) * 16;
    const float* Ap = A + (size_t)(by*128 + cr)*1024 + cc;
    const float* Wp = W + (size_t)(bx*128 + cr)*1024 + cc;

    float acc[2][8][4];
    #pragma unroll
    for (int mi = 0; mi < 2; ++mi)
        #pragma unroll
        for (int ni = 0; ni < 8; ++ni)
            #pragma unroll
            for (int q = 0; q < 4; ++q) acc[mi][ni][q] = 0.f;

    float4 pa[4], pb[4];
    #pragma unroll
    for (int i = 0; i < 4; ++i) {
        pa[i] = *(const float4*)(Ap + 4*i);
        pb[i] = *(const float4*)(Wp + 4*i);
    }
    // STS chunk 0 -> buffer 0
    {
        float* As0 = gsm;
        float* Bs0 = gsm + 4608;
        #pragma unroll
        for (int i = 0; i < 4; ++i) {
            uint32_t* da = (uint32_t*)&As0[cr*36 + cc + 4*i];
            da[0] = f2tf32(pa[i].x); da[1] = f2tf32(pa[i].y);
            da[2] = f2tf32(pa[i].z); da[3] = f2tf32(pa[i].w);
            uint32_t* db = (uint32_t*)&Bs0[cr*36 + cc + 4*i];
            db[0] = f2tf32(pb[i].x); db[1] = f2tf32(pb[i].y);
            db[2] = f2tf32(pb[i].z); db[3] = f2tf32(pb[i].w);
        }
    }
    __syncthreads();

    for (int c = 0; c < 32; ++c) {
        const float* Asb = gsm + (c & 1) * 9216;
        const float* Bsb = Asb + 4608;

        if (c < 31) {   // LDG next chunk early; latency hides under MMAs
            #pragma unroll
            for (int i = 0; i < 4; ++i) {
                pa[i] = *(const float4*)(Ap + (c+1)*32 + 4*i);
                pb[i] = *(const float4*)(Wp + (c+1)*32 + 4*i);
            }
        }

        #pragma unroll
        for (int ks = 0; ks < 4; ++ks) {
            const int k0 = ks * 8;
            uint32_t af[2][4];
            #pragma unroll
            for (int mi = 0; mi < 2; ++mi) {
                const int r = wm + mi*16 + gq;
                af[mi][0] = __float_as_uint(Asb[ r    *36 + k0 + j4    ]);
                af[mi][1] = __float_as_uint(Asb[(r+8)*36 + k0 + j4    ]);
                af[mi][2] = __float_as_uint(Asb[ r    *36 + k0 + j4 + 4]);
                af[mi][3] = __float_as_uint(Asb[(r+8)*36 + k0 + j4 + 4]);
            }
            uint32_t bf[8][2];
            #pragma unroll
            for (int ni = 0; ni < 8; ++ni) {
                const int n = wn + ni*8 + gq;
                bf[ni][0] = __float_as_uint(Bsb[n*36 + k0 + j4    ]);
                bf[ni][1] = __float_as_uint(Bsb[n*36 + k0 + j4 + 4]);
            }
            #pragma unroll
            for (int mi = 0; mi < 2; ++mi)
                #pragma unroll
                for (int ni = 0; ni < 8; ++ni)
                    asm volatile(
                        "mma.sync.aligned.m16n8k8.row.col.f32.tf32.tf32.f32 "
                        "{%0,%1,%2,%3}, {%4,%5,%6,%7}, {%8,%9}, {%0,%1,%2,%3};"
                        : "+f"(acc[mi][ni][0]), "+f"(acc[mi][ni][1]),
                          "+f"(acc[mi][ni][2]), "+f"(acc[mi][ni][3])
                        : "r"(af[mi][0]), "r"(af[mi][1]),
                          "r"(af[mi][2]), "r"(af[mi][3]),
                          "r"(bf[ni][0]), "r"(bf[ni][1]));
        }

        if (c < 31) {   // STS next chunk into other buffer, then single sync
            float* Asn = gsm + ((c+1) & 1) * 9216;
            float* Bsn = Asn + 4608;
            #pragma unroll
            for (int i = 0; i < 4; ++i) {
                uint32_t* da = (uint32_t*)&Asn[cr*36 + cc + 4*i];
                da[0] = f2tf32(pa[i].x); da[1] = f2tf32(pa[i].y);
                da[2] = f2tf32(pa[i].z); da[3] = f2tf32(pa[i].w);
                uint32_t* db = (uint32_t*)&Bsn[cr*36 + cc + 4*i];
                db[0] = f2tf32(pb[i].x); db[1] = f2tf32(pb[i].y);
                db[2] = f2tf32(pb[i].z); db[3] = f2tf32(pb[i].w);
            }
            __syncthreads();
        }
    }

    // ---- epilogues ----
    #pragma unroll
    for (int mi = 0; mi < 2; ++mi) {
        #pragma unroll
        for (int ni = 0; ni < 8; ++ni) {
            const int row = by*128 + wm + mi*16 + gq;
            const int col = bx*128 + wn + ni*8 + 2*j4;
            if (MODE == 0) {
                *(float2*)(C + (size_t)row*1024 + col) =
                    make_float2(acc[mi][ni][0], acc[mi][ni][1]);
                *(float2*)(C + (size_t)(row+8)*1024 + col) =
                    make_float2(acc[mi][ni][2], acc[mi][ni][3]);
            } else if (MODE == 1 || MODE == 2) {
                const float s = (MODE == 1) ? 0.125f : 1.0f;
                const int hh = col >> 6;
                const int d0 = col & 63;
                const int bb = row >> 11;
                const int nq = row & 2047;
                const size_t i0 = ((((size_t)bb*Hh + hh)*Nn + nq)*DHd + d0);
                const size_t i1 = ((((size_t)bb*Hh + hh)*Nn + nq + 8)*DHd + d0);
                float x0 = acc[mi][ni][0]*s, x1 = acc[mi][ni][1]*s;
                float x2 = acc[mi][ni][2]*s, x3 = acc[mi][ni][3]*s;
                uint32_t h0 = pk(x0, x1), h1 = pk(x2, x3);
                *(uint32_t*)(Ch + i0) = h0;
                *(uint32_t*)(Cl + i0) = pk(rlo(x0, h0), rhi(x1, h0));
                *(uint32_t*)(Ch + i1) = h1;
                *(uint32_t*)(Cl + i1) = pk(rlo(x2, h1), rhi(x3, h1));
            } else {   // MODE 3: V transposed (b,h,dh,n)
                const int hh = col >> 6;
                const int d0 = col & 63;
                const int bb = row >> 11;
                const int nq = row & 2047;
                const size_t base = ((size_t)bb*Hh + hh)*DHd;
                #pragma unroll
                for (int e = 0; e < 4; ++e) {
                    const float x = acc[mi][ni][e];
                    const size_t idx = (base + d0 + (e & 1))*Nn + nq + (e >> 1)*8;
                    __nv_bfloat16 h = __float2bfloat16_rn(x);
                    Ch[idx] = h;
                    Cl[idx] = __float2bfloat16_rn(x - __bfloat162float(h));
                }
            }
        }
    }
}

// ========= tensor-core flash attention: bf16x2 3-term, cp.async + ldmatrix ======
// Inputs pre-split bf16 hi/lo: Q (scaled) & K in (b,h,n,dh); V^T in (b,h,dh,n).
// smem buffer (bytes): KH@0 KL@9216 VH@18432 VL@27648 ; stride 36864 ; x2 = 73728.
__global__ __launch_bounds__(256, 1)
void attn_mma(const __nv_bfloat16* __restrict__ Qh, const __nv_bfloat16* __restrict__ Ql,
              const __nv_bfloat16* __restrict__ Kh, const __nv_bfloat16* __restrict__ Kl,
              const __nv_bfloat16* __restrict__ Vh, const __nv_bfloat16* __restrict__ Vl,
              float* __restrict__ O)
{
    extern __shared__ __align__(16) char smb[];
    const uint32_t sb = smem_u32(smb);

    const int bh = blockIdx.y;            // b*H + h
    const int q0 = blockIdx.x * 128;
    const int tid  = threadIdx.x;
    const int w    = tid >> 5;
    const int lane = tid & 31;
    const int gq = lane >> 2;
    const int j4 = lane & 3;

    // per-lane ldmatrix offset: rows lane&7 (stride 144B), (ks pair, b0/b1) select
    const uint32_t lm_off = (uint32_t)((lane & 7) * 144 + ((lane >> 4) & 1) * 32
                                       + ((lane >> 3) & 1) * 16);

    // global tile bases (bytes handled via pointer arithmetic on bf16*)
    const __nv_bfloat16* Kh_b = Kh + (size_t)bh * Nn * DHd;
    const __nv_bfloat16* Kl_b = Kl + (size_t)bh * Nn * DHd;
    const __nv_bfloat16* Vh_b = Vh + (size_t)bh * DHd * Nn;
    const __nv_bfloat16* Vl_b = Vl + (size_t)bh * DHd * Nn;

    // cp.async per-thread mapping: 2 chunks of 16B per array
    const int r0c = (tid*2) >> 3;            // row of chunk 0 (chunks 2t, 2t+1)
    const int c0c = ((tid*2) & 7) * 16;      // byte col of chunk 0 (chunk1 = +16)

    // ---- Q fragments (resident all loop) ----
    uint32_t qhi[4][4], qlo[4][4];
    {
        const __nv_bfloat16* Qbh = Qh + ((size_t)bh * Nn + q0 + 16 * w) * DHd;
        const __nv_bfloat16* Qbl = Ql + ((size_t)bh * Nn + q0 + 16 * w) * DHd;
        #pragma unroll
        for (int ks = 0; ks < 4; ++ks)
            #pragma unroll
            for (int r = 0; r < 4; ++r) {
                const int idx = (gq + (r & 1) * 8) * DHd + 16*ks + 2*j4 + (r >> 1) * 8;
                qhi[ks][r] = *(const uint32_t*)(Qbh + idx);
                qlo[ks][r] = *(const uint32_t*)(Qbl + idx);
            }
    }

    float ctx[8][4];
    #pragma unroll
    for (int ni = 0; ni < 8; ++ni)
        #pragma unroll
        for (int q = 0; q < 4; ++q) ctx[ni][q] = 0.f;
    float m0 = -1e30f, m1 = -1e30f, l0 = 0.f, l1 = 0.f;

    // tile loader: issue 8 cp.asyncs into buffer `buf` for tile kt
    auto issue_tile = [&](int kt, int buf) {
        const uint32_t bb = sb + buf * 36864;
        const char* kh = (const char*)(Kh_b + (size_t)kt * 64 * DHd);
        const char* kl = (const char*)(Kl_b + (size_t)kt * 64 * DHd);
        const char* vh = (const char*)(Vh_b + (size_t)kt * 64);
        const char* vl = (const char*)(Vl_b + (size_t)kt * 64);
        #pragma unroll
        for (int i = 0; i < 2; ++i) {
            const int r  = r0c;                 // both chunks same row
            const int cb = c0c + i * 16;
            const uint32_t so = (uint32_t)(r * 144 + cb);
            cp16(bb +         so, kh + r * 128 + cb);
            cp16(bb + 9216u + so, kl + r * 128 + cb);
            cp16(bb + 18432u + so, vh + (size_t)r * (Nn*2) + cb);
            cp16(bb + 27648u + so, vl + (size_t)r * (Nn*2) + cb);
        }
        CP_COMMIT();
    };

    issue_tile(0, 0);
    CP_WAIT0();
    __syncthreads();

    for (int kt = 0; kt < 32; ++kt) {
        if (kt < 31) issue_tile(kt + 1, (kt + 1) & 1);

        const uint32_t base = sb + (kt & 1) * 36864;

        // ---- S = Q K^T (3-term) ----
        float sacc[8][4];
        #pragma unroll
        for (int ni = 0; ni < 8; ++ni)
            #pragma unroll
            for (int q = 0; q < 4; ++q) sacc[ni][q] = 0.f;

        #pragma unroll
        for (int ni = 0; ni < 8; ++ni) {
            uint32_t kb[8], klr[8];
            LDMX4(kb,     base + ni*1152u + lm_off);          // ks0,1 b0,b1
            LDMX4(kb + 4, base + ni*1152u + 64u + lm_off);    // ks2,3
            LDMX4(klr,     base + 9216u + ni*1152u + lm_off);
            LDMX4(klr + 4, base + 9216u + ni*1152u + 64u + lm_off);
            #pragma unroll
            for (int ks = 0; ks < 4; ++ks) {
                MMA_BF16(sacc[ni], qhi[ks], kb[2*ks],  kb[2*ks+1]);
                MMA_BF16(sacc[ni], qhi[ks], klr[2*ks], klr[2*ks+1]);
                MMA_BF16(sacc[ni], qlo[ks], kb[2*ks],  kb[2*ks+1]);
            }
        }

        // ---- online softmax ----
        float mx0 = -1e30f, mx1 = -1e30f;
        #pragma unroll
        for (int ni = 0; ni < 8; ++ni) {
            mx0 = fmaxf(mx0, fmaxf(sacc[ni][0], sacc[ni][1]));
            mx1 = fmaxf(mx1, fmaxf(sacc[ni][2], sacc[ni][3]));
        }
        mx0 = fmaxf(mx0, __shfl_xor_sync(0xffffffffu, mx0, 1));
        mx0 = fmaxf(mx0, __shfl_xor_sync(0xffffffffu, mx0, 2));
        mx1 = fmaxf(mx1, __shfl_xor_sync(0xffffffffu, mx1, 1));
        mx1 = fmaxf(mx1, __shfl_xor_sync(0xffffffffu, mx1, 2));
        const float mn0 = fmaxf(m0, mx0), mn1 = fmaxf(m1, mx1);
        const float a0 = __expf(m0 - mn0), a1 = __expf(m1 - mn1);
        m0 = mn0; m1 = mn1;

        float rs0 = 0.f, rs1 = 0.f;
        #pragma unroll
        for (int ni = 0; ni < 8; ++ni) {
            sacc[ni][0] = __expf(sacc[ni][0] - mn0);
            sacc[ni][1] = __expf(sacc[ni][1] - mn0);
            sacc[ni][2] = __expf(sacc[ni][2] - mn1);
            sacc[ni][3] = __expf(sacc[ni][3] - mn1);
            rs0 += sacc[ni][0] + sacc[ni][1];
            rs1 += sacc[ni][2] + sacc[ni][3];
        }
        rs0 += __shfl_xor_sync(0xffffffffu, rs0, 1);
        rs0 += __shfl_xor_sync(0xffffffffu, rs0, 2);
        rs1 += __shfl_xor_sync(0xffffffffu, rs1, 1);
        rs1 += __shfl_xor_sync(0xffffffffu, rs1, 2);
        l0 = l0 * a0 + rs0;
        l1 = l1 * a1 + rs1;

        #pragma unroll
        for (int ni = 0; ni < 8; ++ni) {
            ctx[ni][0] *= a0; ctx[ni][1] *= a0;
            ctx[ni][2] *= a1; ctx[ni][3] *= a1;
        }

        // ---- P fragments (register reuse, FA2 layout) ----
        uint32_t phi[4][4], plo[4][4];
        #pragma unroll
        for (int ks = 0; ks < 4; ++ks) {
            const float* t0 = sacc[2*ks];
            const float* t1 = sacc[2*ks + 1];
            uint32_t h;
            h = pk(t0[0], t0[1]); phi[ks][0] = h; plo[ks][0] = pk(rlo(t0[0], h), rhi(t0[1], h));
            h = pk(t0[2], t0[3]); phi[ks][1] = h; plo[ks][1] = pk(rlo(t0[2], h), rhi(t0[3], h));
            h = pk(t1[0], t1[1]); phi[ks][2] = h; plo[ks][2] = pk(rlo(t1[0], h), rhi(t1[1], h));
            h = pk(t1[2], t1[3]); phi[ks][3] = h; plo[ks][3] = pk(rlo(t1[2], h), rhi(t1[3], h));
        }

        // ---- ctx += P V (3-term) ----
        #pragma unroll
        for (int ni = 0; ni < 8; ++ni) {
            uint32_t vb[8], vlr[8];
            LDMX4(vb,     base + 18432u + ni*1152u + lm_off);
            LDMX4(vb + 4, base + 18432u + ni*1152u + 64u + lm_off);
            LDMX4(vlr,     base + 27648u + ni*1152u + lm_off);
            LDMX4(vlr + 4, base + 27648u + ni*1152u + 64u + lm_off);
            #pragma unroll
            for (int ks = 0; ks < 4; ++ks) {
                MMA_BF16(ctx[ni], phi[ks], vb[2*ks],  vb[2*ks+1]);
                MMA_BF16(ctx[ni], phi[ks], vlr[2*ks], vlr[2*ks+1]);
                MMA_BF16(ctx[ni], plo[ks], vb[2*ks],  vb[2*ks+1]);
            }
        }

        if (kt < 31) {
            CP_WAIT0();
            __syncthreads();
        }
    }

    // ---- epilogue: normalize, write (b, n, h*64+dh) fp32 ----
    const int bb = bh >> 4;
    const int hh = bh & 15;
    const float il0 = 1.0f / l0, il1 = 1.0f / l1;
    const int n0 = q0 + 16 * w + gq;
    float* O0 = O + (((size_t)bb * Nn + n0) * Hh + hh) * DHd;
    float* O1 = O + (((size_t)bb * Nn + n0 + 8) * Hh + hh) * DHd;
    #pragma unroll
    for (int ni = 0; ni < 8; ++ni) {
        const int col = 8*ni + 2*j4;
        *(float2*)(O0 + col) = make_float2(ctx[ni][0] * il0, ctx[ni][1] * il0);
        *(float2*)(O1 + col) = make_float2(ctx[ni][2] * il1, ctx[ni][3] * il1);
    }
}

// ---------------- launch ---------------------------------------------------------
extern "C" void kernel_launch(void* const* d_in, const int* in_sizes, int n_in,
                              void* d_out, int out_size)
{
    const float* queries = (const float*)d_in[0];
    const float* keys    = (const float*)d_in[1];
    const float* values  = (const float*)d_in[2];
    const float* Wq      = (const float*)d_in[3];
    const float* Wk      = (const float*)d_in[4];
    const float* Wv      = (const float*)d_in[5];
    const float* Wo      = (const float*)d_in[6];
    float* out = (float*)d_out;

    __nv_bfloat16 *qh, *ql, *kh, *kl, *vh, *vl;
    float* cp;
    cudaGetSymbolAddress((void**)&qh, g_qh);
    cudaGetSymbolAddress((void**)&ql, g_ql);
    cudaGetSymbolAddress((void**)&kh, g_kh);
    cudaGetSymbolAddress((void**)&kl, g_kl);
    cudaGetSymbolAddress((void**)&vh, g_vh);
    cudaGetSymbolAddress((void**)&vl, g_vl);
    cudaGetSymbolAddress((void**)&cp, g_ctx);

    const int gsmem = 2 * 2 * 4608 * (int)sizeof(float);   // 73728 B
    cudaFuncSetAttribute(gemm_mma<0>, cudaFuncAttributeMaxDynamicSharedMemorySize, gsmem);
    cudaFuncSetAttribute(gemm_mma<1>, cudaFuncAttributeMaxDynamicSharedMemorySize, gsmem);
    cudaFuncSetAttribute(gemm_mma<2>, cudaFuncAttributeMaxDynamicSharedMemorySize, gsmem);
    cudaFuncSetAttribute(gemm_mma<3>, cudaFuncAttributeMaxDynamicSharedMemorySize, gsmem);

    dim3 ggrid(1024/128, MTOT/128);   // (8, 64)
    gemm_mma<1><<<ggrid, 256, gsmem>>>(queries, Wq, nullptr, qh, ql);
    gemm_mma<2><<<ggrid, 256, gsmem>>>(keys,    Wk, nullptr, kh, kl);
    gemm_mma<3><<<ggrid, 256, gsmem>>>(values,  Wv, nullptr, vh, vl);

    const int asmem = 2 * 36864;      // 73728 B
    cudaFuncSetAttribute(attn_mma,
                         cudaFuncAttributeMaxDynamicSharedMemorySize, asmem);
    dim3 agrid(Nn/128, Bb*Hh);        // (16, 64)
    attn_mma<<<agrid, 256, asmem>>>(qh, ql, kh, kl, vh, vl, cp);

    gemm_mma<0><<<ggrid, 256, gsmem>>>(cp, Wo, out, nullptr, nullptr);
}

// round 17
// speedup vs baseline: 1.0001x; 1.0001x over previous
#include <cuda_runtime.h>
#include <cuda_bf16.h>
#include <cstdint>
#include <cstddef>

#define Hh   16
#define Dd   1024
#define DHd  64
#define Bb   4
#define Nn   2048
#define MTOT (Bb*Nn)   // 8192

// ---------------- scratch (static device globals; no allocation) ----------------
__device__ __nv_bfloat16 g_qh[(size_t)Bb*Hh*Nn*DHd];   // (b,h,n,dh)  Q*0.125 hi
__device__ __nv_bfloat16 g_ql[(size_t)Bb*Hh*Nn*DHd];   //             Q*0.125 lo
__device__ __nv_bfloat16 g_kh[(size_t)Bb*Hh*Nn*DHd];   // (b,h,n,dh)  K hi
__device__ __nv_bfloat16 g_kl[(size_t)Bb*Hh*Nn*DHd];
__device__ __nv_bfloat16 g_vh[(size_t)Bb*Hh*Nn*DHd];   // (b,h,dh,n)  V^T hi
__device__ __nv_bfloat16 g_vl[(size_t)Bb*Hh*Nn*DHd];
__device__ float g_ctx[(size_t)MTOT*Dd];                // (b,n,h*dh)

__device__ __forceinline__ uint32_t f2tf32(float x) {
    uint32_t r;
    asm("cvt.rna.tf32.f32 %0, %1;" : "=r"(r) : "f"(x));
    return r;
}
// pack two floats -> bf16x2 (lo half = first element)
__device__ __forceinline__ uint32_t pk(float lo, float hi) {
    __nv_bfloat162 h = __float22bfloat162_rn(make_float2(lo, hi));
    return *(uint32_t*)&h;
}
__device__ __forceinline__ float rlo(float f, uint32_t p) { return f - __uint_as_float(p << 16); }
__device__ __forceinline__ float rhi(float f, uint32_t p) { return f - __uint_as_float(p & 0xffff0000u); }

#define MMA_BF16(d, a, b0, b1) \
    asm volatile("mma.sync.aligned.m16n8k16.row.col.f32.bf16.bf16.f32 " \
        "{%0,%1,%2,%3},{%4,%5,%6,%7},{%8,%9},{%0,%1,%2,%3};" \
        : "+f"((d)[0]), "+f"((d)[1]), "+f"((d)[2]), "+f"((d)[3]) \
        : "r"((a)[0]), "r"((a)[1]), "r"((a)[2]), "r"((a)[3]), "r"(b0), "r"(b1))

#define LDMX4(r, addr) \
    asm volatile("ldmatrix.sync.aligned.m8n8.x4.shared.b16 {%0,%1,%2,%3}, [%4];" \
        : "=r"((r)[0]), "=r"((r)[1]), "=r"((r)[2]), "=r"((r)[3]) : "r"(addr))

__device__ __forceinline__ uint32_t smem_u32(const void* p) {
    uint32_t a;
    asm("{ .reg .u64 t; cvta.to.shared.u64 t, %1; cvt.u32.u64 %0, t; }" : "=r"(a) : "l"(p));
    return a;
}
__device__ __forceinline__ void cp16(uint32_t s, const void* g) {
    asm volatile("cp.async.ca.shared.global [%0], [%1], 16;" :: "r"(s), "l"(g));
}
#define CP_COMMIT() asm volatile("cp.async.commit_group;")
#define CP_WAIT0()  asm volatile("cp.async.wait_group 0;")

// ====== tf32 mma.sync NT GEMM: C = A(M,K) * W(N,K)^T ; 128x128 tile, K=1024 =====
// Double-buffered smem (dynamic 73728 B). 8 warps 4(M)x2(N), warp tile 32x64.
// MODE 0: C fp32 row-major (M x 1024).
// MODE 1: Q -> (b,h,n,dh) bf16 hi/lo, scaled 0.125.   MODE 2: K -> same, unscaled.
// MODE 3: V -> (b,h,dh,n) bf16 hi/lo (transposed).
template<int MODE>
__global__ __launch_bounds__(256)
void gemm_mma(const float* __restrict__ A, const float* __restrict__ W,
              float* __restrict__ C, __nv_bfloat16* __restrict__ Ch,
              __nv_bfloat16* __restrict__ Cl)
{
    extern __shared__ float gsm[];   // [2][A 128*36 | B 128*36]

    const int tid  = threadIdx.x;
    const int wid  = tid >> 5;
    const int lane = tid & 31;
    const int bx = blockIdx.x;     // N tile (0..7)
    const int by = blockIdx.y;     // M tile (0..63)

    const int wm = (wid >> 1) * 32;
    const int wn = (wid & 1)  * 64;
    const int gq = lane >> 2;
    const int j4 = lane & 3;

    const int cr = tid >> 1;
    const int cc = (tid & 1) * 16;
    const float* Ap = A + (size_t)(by*128 + cr)*1024 + cc;
    const float* Wp = W + (size_t)(bx*128 + cr)*1024 + cc;

    float acc[2][8][4];
    #pragma unroll
    for (int mi = 0; mi < 2; ++mi)
        #pragma unroll
        for (int ni = 0; ni < 8; ++ni)
            #pragma unroll
            for (int q = 0; q < 4; ++q) acc[mi][ni][q] = 0.f;

    float4 pa[4], pb[4];
    #pragma unroll
    for (int i = 0; i < 4; ++i) {
        pa[i] = *(const float4*)(Ap + 4*i);
        pb[i] = *(const float4*)(Wp + 4*i);
    }
    // STS chunk 0 -> buffer 0
    {
        float* As0 = gsm;
        float* Bs0 = gsm + 4608;
        #pragma unroll
        for (int i = 0; i < 4; ++i) {
            uint32_t* da = (uint32_t*)&As0[cr*36 + cc + 4*i];
            da[0] = f2tf32(pa[i].x); da[1] = f2tf32(pa[i].y);
            da[2] = f2tf32(pa[i].z); da[3] = f2tf32(pa[i].w);
            uint32_t* db = (uint32_t*)&Bs0[cr*36 + cc + 4*i];
            db[0] = f2tf32(pb[i].x); db[1] = f2tf32(pb[i].y);
            db[2] = f2tf32(pb[i].z); db[3] = f2tf32(pb[i].w);
        }
    }
    __syncthreads();

    for (int c = 0; c < 32; ++c) {
        const float* Asb = gsm + (c & 1) * 9216;
        const float* Bsb = Asb + 4608;

        if (c < 31) {   // LDG next chunk early; latency hides under MMAs
            #pragma unroll
            for (int i = 0; i < 4; ++i) {
                pa[i] = *(const float4*)(Ap + (c+1)*32 + 4*i);
                pb[i] = *(const float4*)(Wp + (c+1)*32 + 4*i);
            }
        }

        #pragma unroll
        for (int ks = 0; ks < 4; ++ks) {
            const int k0 = ks * 8;
            uint32_t af[2][4];
            #pragma unroll
            for (int mi = 0; mi < 2; ++mi) {
                const int r = wm + mi*16 + gq;
                af[mi][0] = __float_as_uint(Asb[ r    *36 + k0 + j4    ]);
                af[mi][1] = __float_as_uint(Asb[(r+8)*36 + k0 + j4    ]);
                af[mi][2] = __float_as_uint(Asb[ r    *36 + k0 + j4 + 4]);
                af[mi][3] = __float_as_uint(Asb[(r+8)*36 + k0 + j4 + 4]);
            }
            uint32_t bf[8][2];
            #pragma unroll
            for (int ni = 0; ni < 8; ++ni) {
                const int n = wn + ni*8 + gq;
                bf[ni][0] = __float_as_uint(Bsb[n*36 + k0 + j4    ]);
                bf[ni][1] = __float_as_uint(Bsb[n*36 + k0 + j4 + 4]);
            }
            #pragma unroll
            for (int mi = 0; mi < 2; ++mi)
                #pragma unroll
                for (int ni = 0; ni < 8; ++ni)
                    asm volatile(
                        "mma.sync.aligned.m16n8k8.row.col.f32.tf32.tf32.f32 "
                        "{%0,%1,%2,%3}, {%4,%5,%6,%7}, {%8,%9}, {%0,%1,%2,%3};"
                        : "+f"(acc[mi][ni][0]), "+f"(acc[mi][ni][1]),
                          "+f"(acc[mi][ni][2]), "+f"(acc[mi][ni][3])
                        : "r"(af[mi][0]), "r"(af[mi][1]),
                          "r"(af[mi][2]), "r"(af[mi][3]),
                          "r"(bf[ni][0]), "r"(bf[ni][1]));
        }

        if (c < 31) {   // STS next chunk into other buffer, then single sync
            float* Asn = gsm + ((c+1) & 1) * 9216;
            float* Bsn = Asn + 4608;
            #pragma unroll
            for (int i = 0; i < 4; ++i) {
                uint32_t* da = (uint32_t*)&Asn[cr*36 + cc + 4*i];
                da[0] = f2tf32(pa[i].x); da[1] = f2tf32(pa[i].y);
                da[2] = f2tf32(pa[i].z); da[3] = f2tf32(pa[i].w);
                uint32_t* db = (uint32_t*)&Bsn[cr*36 + cc + 4*i];
                db[0] = f2tf32(pb[i].x); db[1] = f2tf32(pb[i].y);
                db[2] = f2tf32(pb[i].z); db[3] = f2tf32(pb[i].w);
            }
            __syncthreads();
        }
    }

    // ---- epilogues ----
    #pragma unroll
    for (int mi = 0; mi < 2; ++mi) {
        #pragma unroll
        for (int ni = 0; ni < 8; ++ni) {
            const int row = by*128 + wm + mi*16 + gq;
            const int col = bx*128 + wn + ni*8 + 2*j4;
            if (MODE == 0) {
                *(float2*)(C + (size_t)row*1024 + col) =
                    make_float2(acc[mi][ni][0], acc[mi][ni][1]);
                *(float2*)(C + (size_t)(row+8)*1024 + col) =
                    make_float2(acc[mi][ni][2], acc[mi][ni][3]);
            } else if (MODE == 1 || MODE == 2) {
                const float s = (MODE == 1) ? 0.125f : 1.0f;
                const int hh = col >> 6;
                const int d0 = col & 63;
                const int bb = row >> 11;
                const int nq = row & 2047;
                const size_t i0 = ((((size_t)bb*Hh + hh)*Nn + nq)*DHd + d0);
                const size_t i1 = ((((size_t)bb*Hh + hh)*Nn + nq + 8)*DHd + d0);
                float x0 = acc[mi][ni][0]*s, x1 = acc[mi][ni][1]*s;
                float x2 = acc[mi][ni][2]*s, x3 = acc[mi][ni][3]*s;
                uint32_t h0 = pk(x0, x1), h1 = pk(x2, x3);
                *(uint32_t*)(Ch + i0) = h0;
                *(uint32_t*)(Cl + i0) = pk(rlo(x0, h0), rhi(x1, h0));
                *(uint32_t*)(Ch + i1) = h1;
                *(uint32_t*)(Cl + i1) = pk(rlo(x2, h1), rhi(x3, h1));
            } else {   // MODE 3: V transposed (b,h,dh,n)
                const int hh = col >> 6;
                const int d0 = col & 63;
                const int bb = row >> 11;
                const int nq = row & 2047;
                const size_t base = ((size_t)bb*Hh + hh)*DHd;
                #pragma unroll
                for (int e = 0; e < 4; ++e) {
                    const float x = acc[mi][ni][e];
                    const size_t idx = (base + d0 + (e & 1))*Nn + nq + (e >> 1)*8;
                    __nv_bfloat16 h = __float2bfloat16_rn(x);
                    Ch[idx] = h;
                    Cl[idx] = __float2bfloat16_rn(x - __bfloat162float(h));
                }
            }
        }
    }
}

// ========= tensor-core flash attention: bf16x2 3-term, cp.async + ldmatrix ======
// Inputs pre-split bf16 hi/lo: Q (scaled) & K in (b,h,n,dh); V^T in (b,h,dh,n).
// smem buffer (bytes): KH@0 KL@9216 VH@18432 VL@27648 ; stride 36864 ; x2 = 73728.
__global__ __launch_bounds__(256, 1)
void attn_mma(const __nv_bfloat16* __restrict__ Qh, const __nv_bfloat16* __restrict__ Ql,
              const __nv_bfloat16* __restrict__ Kh, const __nv_bfloat16* __restrict__ Kl,
              const __nv_bfloat16* __restrict__ Vh, const __nv_bfloat16* __restrict__ Vl,
              float* __restrict__ O)
{
    extern __shared__ __align__(16) char smb[];
    const uint32_t sb = smem_u32(smb);

    const int bh = blockIdx.y;            // b*H + h
    const int q0 = blockIdx.x * 128;
    const int tid  = threadIdx.x;
    const int w    = tid >> 5;
    const int lane = tid & 31;
    const int gq = lane >> 2;
    const int j4 = lane & 3;

    // per-lane ldmatrix offset: rows lane&7 (stride 144B), (ks pair, b0/b1) select
    const uint32_t lm_off = (uint32_t)((lane & 7) * 144 + ((lane >> 4) & 1) * 32
                                       + ((lane >> 3) & 1) * 16);

    // global tile bases (bytes handled via pointer arithmetic on bf16*)
    const __nv_bfloat16* Kh_b = Kh + (size_t)bh * Nn * DHd;
    const __nv_bfloat16* Kl_b = Kl + (size_t)bh * Nn * DHd;
    const __nv_bfloat16* Vh_b = Vh + (size_t)bh * DHd * Nn;
    const __nv_bfloat16* Vl_b = Vl + (size_t)bh * DHd * Nn;

    // cp.async per-thread mapping: 2 chunks of 16B per array
    const int r0c = (tid*2) >> 3;            // row of chunk 0 (chunks 2t, 2t+1)
    const int c0c = ((tid*2) & 7) * 16;      // byte col of chunk 0 (chunk1 = +16)

    // ---- Q fragments (resident all loop) ----
    uint32_t qhi[4][4], qlo[4][4];
    {
        const __nv_bfloat16* Qbh = Qh + ((size_t)bh * Nn + q0 + 16 * w) * DHd;
        const __nv_bfloat16* Qbl = Ql + ((size_t)bh * Nn + q0 + 16 * w) * DHd;
        #pragma unroll
        for (int ks = 0; ks < 4; ++ks)
            #pragma unroll
            for (int r = 0; r < 4; ++r) {
                const int idx = (gq + (r & 1) * 8) * DHd + 16*ks + 2*j4 + (r >> 1) * 8;
                qhi[ks][r] = *(const uint32_t*)(Qbh + idx);
                qlo[ks][r] = *(const uint32_t*)(Qbl + idx);
            }
    }

    float ctx[8][4];
    #pragma unroll
    for (int ni = 0; ni < 8; ++ni)
        #pragma unroll
        for (int q = 0; q < 4; ++q) ctx[ni][q] = 0.f;
    float m0 = -1e30f, m1 = -1e30f, l0 = 0.f, l1 = 0.f;

    // tile loader: issue 8 cp.asyncs into buffer `buf` for tile kt
    auto issue_tile = [&](int kt, int buf) {
        const uint32_t bb = sb + buf * 36864;
        const char* kh = (const char*)(Kh_b + (size_t)kt * 64 * DHd);
        const char* kl = (const char*)(Kl_b + (size_t)kt * 64 * DHd);
        const char* vh = (const char*)(Vh_b + (size_t)kt * 64);
        const char* vl = (const char*)(Vl_b + (size_t)kt * 64);
        #pragma unroll
        for (int i = 0; i < 2; ++i) {
            const int r  = r0c;                 // both chunks same row
            const int cb = c0c + i * 16;
            const uint32_t so = (uint32_t)(r * 144 + cb);
            cp16(bb +         so, kh + r * 128 + cb);
            cp16(bb + 9216u + so, kl + r * 128 + cb);
            cp16(bb + 18432u + so, vh + (size_t)r * (Nn*2) + cb);
            cp16(bb + 27648u + so, vl + (size_t)r * (Nn*2) + cb);
        }
        CP_COMMIT();
    };

    issue_tile(0, 0);
    CP_WAIT0();
    __syncthreads();

    for (int kt = 0; kt < 32; ++kt) {
        if (kt < 31) issue_tile(kt + 1, (kt + 1) & 1);

        const uint32_t base = sb + (kt & 1) * 36864;

        // ---- S = Q K^T (3-term) ----
        float sacc[8][4];
        #pragma unroll
        for (int ni = 0; ni < 8; ++ni)
            #pragma unroll
            for (int q = 0; q < 4; ++q) sacc[ni][q] = 0.f;

        #pragma unroll
        for (int ni = 0; ni < 8; ++ni) {
            uint32_t kb[8], klr[8];
            LDMX4(kb,     base + ni*1152u + lm_off);          // ks0,1 b0,b1
            LDMX4(kb + 4, base + ni*1152u + 64u + lm_off);    // ks2,3
            LDMX4(klr,     base + 9216u + ni*1152u + lm_off);
            LDMX4(klr + 4, base + 9216u + ni*1152u + 64u + lm_off);
            #pragma unroll
            for (int ks = 0; ks < 4; ++ks) {
                MMA_BF16(sacc[ni], qhi[ks], kb[2*ks],  kb[2*ks+1]);
                MMA_BF16(sacc[ni], qhi[ks], klr[2*ks], klr[2*ks+1]);
                MMA_BF16(sacc[ni], qlo[ks], kb[2*ks],  kb[2*ks+1]);
            }
        }

        // ---- online softmax ----
        float mx0 = -1e30f, mx1 = -1e30f;
        #pragma unroll
        for (int ni = 0; ni < 8; ++ni) {
            mx0 = fmaxf(mx0, fmaxf(sacc[ni][0], sacc[ni][1]));
            mx1 = fmaxf(mx1, fmaxf(sacc[ni][2], sacc[ni][3]));
        }
        mx0 = fmaxf(mx0, __shfl_xor_sync(0xffffffffu, mx0, 1));
        mx0 = fmaxf(mx0, __shfl_xor_sync(0xffffffffu, mx0, 2));
        mx1 = fmaxf(mx1, __shfl_xor_sync(0xffffffffu, mx1, 1));
        mx1 = fmaxf(mx1, __shfl_xor_sync(0xffffffffu, mx1, 2));
        const float mn0 = fmaxf(m0, mx0), mn1 = fmaxf(m1, mx1);
        const float a0 = __expf(m0 - mn0), a1 = __expf(m1 - mn1);
        m0 = mn0; m1 = mn1;

        float rs0 = 0.f, rs1 = 0.f;
        #pragma unroll
        for (int ni = 0; ni < 8; ++ni) {
            sacc[ni][0] = __expf(sacc[ni][0] - mn0);
            sacc[ni][1] = __expf(sacc[ni][1] - mn0);
            sacc[ni][2] = __expf(sacc[ni][2] - mn1);
            sacc[ni][3] = __expf(sacc[ni][3] - mn1);
            rs0 += sacc[ni][0] + sacc[ni][1];
            rs1 += sacc[ni][2] + sacc[ni][3];
        }
        rs0 += __shfl_xor_sync(0xffffffffu, rs0, 1);
        rs0 += __shfl_xor_sync(0xffffffffu, rs0, 2);
        rs1 += __shfl_xor_sync(0xffffffffu, rs1, 1);
        rs1 += __shfl_xor_sync(0xffffffffu, rs1, 2);
        l0 = l0 * a0 + rs0;
        l1 = l1 * a1 + rs1;

        #pragma unroll
        for (int ni = 0; ni < 8; ++ni) {
            ctx[ni][0] *= a0; ctx[ni][1] *= a0;
            ctx[ni][2] *= a1; ctx[ni][3] *= a1;
        }

        // ---- P fragments (register reuse, FA2 layout) ----
        uint32_t phi[4][4], plo[4][4];
        #pragma unroll
        for (int ks = 0; ks < 4; ++ks) {
            const float* t0 = sacc[2*ks];
            const float* t1 = sacc[2*ks + 1];
            uint32_t h;
            h = pk(t0[0], t0[1]); phi[ks][0] = h; plo[ks][0] = pk(rlo(t0[0], h), rhi(t0[1], h));
            h = pk(t0[2], t0[3]); phi[ks][1] = h; plo[ks][1] = pk(rlo(t0[2], h), rhi(t0[3], h));
            h = pk(t1[0], t1[1]); phi[ks][2] = h; plo[ks][2] = pk(rlo(t1[0], h), rhi(t1[1], h));
            h = pk(t1[2], t1[3]); phi[ks][3] = h; plo[ks][3] = pk(rlo(t1[2], h), rhi(t1[3], h));
        }

        // ---- ctx += P V (3-term) ----
        #pragma unroll
        for (int ni = 0; ni < 8; ++ni) {
            uint32_t vb[8], vlr[8];
            LDMX4(vb,     base + 18432u + ni*1152u + lm_off);
            LDMX4(vb + 4, base + 18432u + ni*1152u + 64u + lm_off);
            LDMX4(vlr,     base + 27648u + ni*1152u + lm_off);
            LDMX4(vlr + 4, base + 27648u + ni*1152u + 64u + lm_off);
            #pragma unroll
            for (int ks = 0; ks < 4; ++ks) {
                MMA_BF16(ctx[ni], phi[ks], vb[2*ks],  vb[2*ks+1]);
                MMA_BF16(ctx[ni], phi[ks], vlr[2*ks], vlr[2*ks+1]);
                MMA_BF16(ctx[ni], plo[ks], vb[2*ks],  vb[2*ks+1]);
            }
        }

        if (kt < 31) {
            CP_WAIT0();
            __syncthreads();
        }
    }

    // ---- epilogue: normalize, write (b, n, h*64+dh) fp32 ----
    const int bb = bh >> 4;
    const int hh = bh & 15;
    const float il0 = 1.0f / l0, il1 = 1.0f / l1;
    const int n0 = q0 + 16 * w + gq;
    float* O0 = O + (((size_t)bb * Nn + n0) * Hh + hh) * DHd;
    float* O1 = O + (((size_t)bb * Nn + n0 + 8) * Hh + hh) * DHd;
    #pragma unroll
    for (int ni = 0; ni < 8; ++ni) {
        const int col = 8*ni + 2*j4;
        *(float2*)(O0 + col) = make_float2(ctx[ni][0] * il0, ctx[ni][1] * il0);
        *(float2*)(O1 + col) = make_float2(ctx[ni][2] * il1, ctx[ni][3] * il1);
    }
}

// ---------------- launch ---------------------------------------------------------
extern "C" void kernel_launch(void* const* d_in, const int* in_sizes, int n_in,
                              void* d_out, int out_size)
{
    const float* queries = (const float*)d_in[0];
    const float* keys    = (const float*)d_in[1];
    const float* values  = (const float*)d_in[2];
    const float* Wq      = (const float*)d_in[3];
    const float* Wk      = (const float*)d_in[4];
    const float* Wv      = (const float*)d_in[5];
    const float* Wo      = (const float*)d_in[6];
    float* out = (float*)d_out;

    __nv_bfloat16 *qh, *ql, *kh, *kl, *vh, *vl;
    float* cp;
    cudaGetSymbolAddress((void**)&qh, g_qh);
    cudaGetSymbolAddress((void**)&ql, g_ql);
    cudaGetSymbolAddress((void**)&kh, g_kh);
    cudaGetSymbolAddress((void**)&kl, g_kl);
    cudaGetSymbolAddress((void**)&vh, g_vh);
    cudaGetSymbolAddress((void**)&vl, g_vl);
    cudaGetSymbolAddress((void**)&cp, g_ctx);

    const int gsmem = 2 * 2 * 4608 * (int)sizeof(float);   // 73728 B
    cudaFuncSetAttribute(gemm_mma<0>, cudaFuncAttributeMaxDynamicSharedMemorySize, gsmem);
    cudaFuncSetAttribute(gemm_mma<1>, cudaFuncAttributeMaxDynamicSharedMemorySize, gsmem);
    cudaFuncSetAttribute(gemm_mma<2>, cudaFuncAttributeMaxDynamicSharedMemorySize, gsmem);
    cudaFuncSetAttribute(gemm_mma<3>, cudaFuncAttributeMaxDynamicSharedMemorySize, gsmem);

    dim3 ggrid(1024/128, MTOT/128);   // (8, 64)
    gemm_mma<1><<<ggrid, 256, gsmem>>>(queries, Wq, nullptr, qh, ql);
    gemm_mma<2><<<ggrid, 256, gsmem>>>(keys,    Wk, nullptr, kh, kl);
    gemm_mma<3><<<ggrid, 256, gsmem>>>(values,  Wv, nullptr, vh, vl);

    const int asmem = 2 * 36864;      // 73728 B
    cudaFuncSetAttribute(attn_mma,
                         cudaFuncAttributeMaxDynamicSharedMemorySize, asmem);
    dim3 agrid(Nn/128, Bb*Hh);        // (16, 64)
    attn_mma<<<agrid, 256, asmem>>>(qh, ql, kh, kl, vh, vl, cp);

    gemm_mma<0><<<ggrid, 256, gsmem>>>(cp, Wo, out, nullptr, nullptr);
}